// round 1
// baseline (speedup 1.0000x reference)
#include <cuda_runtime.h>
#include <math.h>

#define Nn     100000
#define Ee     1600000
#define NFEAT  512
#define NHID   256
#define NCLASS 40
#define KHOP   10
#define ALPHA  0.1f

// ---------------- scratch (static __device__ — no allocations allowed) ----------------
__device__ float g_h1[(size_t)Nn * NHID];     // relu(x@W1+b1)   [N,256]
__device__ float g_h [(size_t)Nn * NCLASS];   // h1@W2+b2        [N,40]
__device__ float g_zA[(size_t)Nn * NCLASS];
__device__ float g_zB[(size_t)Nn * NCLASS];
__device__ int   g_counts[Nn];
__device__ int   g_rowptr[Nn + 1];
__device__ int   g_cursor[Nn];
__device__ int   g_csr_src[Ee];
__device__ float g_csr_val[Ee];

// ---------------- GEMM1: h1 = relu(x @ W1 + b1), [N,512]x[512,256] ----------------
// 128x128 tile, BK=8, 256 threads, 8x8 register micro-tile, float4 global loads.
__global__ __launch_bounds__(256) void gemm1_relu_kernel(
    const float* __restrict__ A, const float* __restrict__ B,
    const float* __restrict__ bias)
{
  __shared__ float As[8 * 128];   // transposed: As[k][m]
  __shared__ float Bs[8 * 128];
  const int tid  = threadIdx.x;
  const int cCol = blockIdx.x;    // 0..1   (256/128)
  const int cRow = blockIdx.y;    // 0..781
  const int threadCol = tid % 16;
  const int threadRow = tid / 16;
  const int innerRowA = tid / 2;  // 0..127
  const int innerColA = tid % 2;  // 0..1
  const int innerRowB = tid / 32; // 0..7
  const int innerColB = tid % 32; // 0..31
  const int aRow = cRow * 128 + innerRowA;

  float acc[64];
  #pragma unroll
  for (int i = 0; i < 64; i++) acc[i] = 0.f;
  float regM[8], regN[8];

  for (int kt = 0; kt < NFEAT; kt += 8) {
    float4 a4;
    if (aRow < Nn)
      a4 = *reinterpret_cast<const float4*>(A + (size_t)aRow * NFEAT + kt + innerColA * 4);
    else
      a4 = make_float4(0.f, 0.f, 0.f, 0.f);
    As[(innerColA * 4 + 0) * 128 + innerRowA] = a4.x;
    As[(innerColA * 4 + 1) * 128 + innerRowA] = a4.y;
    As[(innerColA * 4 + 2) * 128 + innerRowA] = a4.z;
    As[(innerColA * 4 + 3) * 128 + innerRowA] = a4.w;
    float4 b4 = *reinterpret_cast<const float4*>(
        B + (size_t)(kt + innerRowB) * NHID + cCol * 128 + innerColB * 4);
    *reinterpret_cast<float4*>(&Bs[innerRowB * 128 + innerColB * 4]) = b4;
    __syncthreads();
    #pragma unroll
    for (int k = 0; k < 8; k++) {
      #pragma unroll
      for (int i = 0; i < 8; i++) regM[i] = As[k * 128 + threadRow * 8 + i];
      #pragma unroll
      for (int j = 0; j < 8; j++) regN[j] = Bs[k * 128 + threadCol * 8 + j];
      #pragma unroll
      for (int i = 0; i < 8; i++)
        #pragma unroll
        for (int j = 0; j < 8; j++)
          acc[i * 8 + j] += regM[i] * regN[j];
    }
    __syncthreads();
  }
  const int colBase = cCol * 128 + threadCol * 8;
  #pragma unroll
  for (int i = 0; i < 8; i++) {
    int row = cRow * 128 + threadRow * 8 + i;
    if (row < Nn) {
      #pragma unroll
      for (int j = 0; j < 8; j++) {
        float v = acc[i * 8 + j] + bias[colBase + j];
        g_h1[(size_t)row * NHID + colBase + j] = fmaxf(v, 0.f);
      }
    }
  }
}

// ---------------- GEMM2: h = h1 @ W2 + b2, [N,256]x[256,40] ----------------
// 48 rows per block, k tiled by 64, thread = 4 rows x 2 classes (240 active of 256).
__global__ __launch_bounds__(256) void gemm2_kernel(
    const float* __restrict__ W2, const float* __restrict__ b2)
{
  __shared__ float h1s[48 * 68];       // padded stride 68 (bank-conflict break, 16B aligned)
  __shared__ float w2s[64 * NCLASS];
  const int t    = threadIdx.x;
  const int base = blockIdx.x * 48;
  const int cp   = t % 20;             // class pair -> classes 2*cp, 2*cp+1
  const int rg   = t / 20;             // row group (valid < 12) -> rows rg*4 .. rg*4+3
  float acc[4][2] = {{0.f,0.f},{0.f,0.f},{0.f,0.f},{0.f,0.f}};

  for (int kc = 0; kc < NHID; kc += 64) {
    for (int idx = t; idx < 48 * 16; idx += 256) {
      int r = idx / 16, c4 = idx % 16;
      int row = base + r;
      float4 v = make_float4(0.f, 0.f, 0.f, 0.f);
      if (row < Nn)
        v = *reinterpret_cast<const float4*>(&g_h1[(size_t)row * NHID + kc + c4 * 4]);
      *reinterpret_cast<float4*>(&h1s[r * 68 + c4 * 4]) = v;
    }
    for (int idx = t; idx < 64 * NCLASS; idx += 256)
      w2s[idx] = W2[(size_t)(kc + idx / NCLASS) * NCLASS + idx % NCLASS];
    __syncthreads();
    if (rg < 12) {
      #pragma unroll 8
      for (int k = 0; k < 64; k++) {
        float w0 = w2s[k * NCLASS + cp * 2];
        float w1 = w2s[k * NCLASS + cp * 2 + 1];
        #pragma unroll
        for (int rr = 0; rr < 4; rr++) {
          float hv = h1s[(rg * 4 + rr) * 68 + k];
          acc[rr][0] += hv * w0;
          acc[rr][1] += hv * w1;
        }
      }
    }
    __syncthreads();
  }
  if (rg < 12) {
    float bb0 = b2[cp * 2], bb1 = b2[cp * 2 + 1];
    #pragma unroll
    for (int rr = 0; rr < 4; rr++) {
      int row = base + rg * 4 + rr;
      if (row < Nn) {
        g_h[(size_t)row * NCLASS + cp * 2]     = acc[rr][0] + bb0;
        g_h[(size_t)row * NCLASS + cp * 2 + 1] = acc[rr][1] + bb1;
      }
    }
  }
}

// ---------------- CSR build (by dst) ----------------
__global__ void zero_counts_kernel() {
  int i = blockIdx.x * blockDim.x + threadIdx.x;
  if (i < Nn) g_counts[i] = 0;
}

__global__ void hist_kernel(const int* __restrict__ edst) {
  int e = blockIdx.x * blockDim.x + threadIdx.x;
  if (e < Ee) atomicAdd(&g_counts[edst[e]], 1);
}

// Single-block exclusive scan over 100K counts (98 chunks of 1024, Hillis-Steele).
__global__ __launch_bounds__(1024) void scan_kernel() {
  __shared__ int sh[1024];
  __shared__ int s_carry;
  if (threadIdx.x == 0) s_carry = 0;
  __syncthreads();
  for (int bb = 0; bb < Nn; bb += 1024) {
    int i = bb + threadIdx.x;
    int v = (i < Nn) ? g_counts[i] : 0;
    sh[threadIdx.x] = v;
    __syncthreads();
    for (int off = 1; off < 1024; off <<= 1) {
      int tv = (threadIdx.x >= off) ? sh[threadIdx.x - off] : 0;
      __syncthreads();
      sh[threadIdx.x] += tv;
      __syncthreads();
    }
    int exc = sh[threadIdx.x] - v + s_carry;
    if (i < Nn) { g_rowptr[i] = exc; g_cursor[i] = exc; }
    __syncthreads();
    if (threadIdx.x == 1023) s_carry += sh[1023];
    __syncthreads();
  }
  if (threadIdx.x == 0) g_rowptr[Nn] = s_carry;
}

__global__ void scatter_kernel(const int* __restrict__ esrc, const int* __restrict__ edst,
                               const float* __restrict__ eval) {
  int e = blockIdx.x * blockDim.x + threadIdx.x;
  if (e < Ee) {
    int d = edst[e];
    int p = atomicAdd(&g_cursor[d], 1);
    g_csr_src[p] = esrc[e];
    g_csr_val[p] = eval[e];
  }
}

// ---------------- APPNP propagation: z = 0.9 * (A z) + 0.1 * h ----------------
// One warp per dst row: lanes 0..31 carry class c=lane, lanes 0..7 also c=32+lane.
// Atomic-free: CSR rows are contiguous per dst.
__global__ __launch_bounds__(256) void spmm_kernel(int it) {
  const float* zin  = (it == 0) ? g_h : ((it & 1) ? g_zA : g_zB);
  float*       zout = (it & 1) ? g_zB : g_zA;
  int warp = threadIdx.x >> 5, lane = threadIdx.x & 31;
  int row = blockIdx.x * 8 + warp;
  if (row >= Nn) return;
  int s = g_rowptr[row], e = g_rowptr[row + 1];
  float acc0 = 0.f, acc1 = 0.f;
  for (int i = s; i < e; i++) {
    int   src = g_csr_src[i];
    float v   = g_csr_val[i];
    const float* zr = zin + (size_t)src * NCLASS;
    acc0 += v * zr[lane];
    if (lane < 8) acc1 += v * zr[32 + lane];
  }
  const float* hr = g_h + (size_t)row * NCLASS;
  float* o = zout + (size_t)row * NCLASS;
  o[lane] = (1.f - ALPHA) * acc0 + ALPHA * hr[lane];
  if (lane < 8) o[32 + lane] = (1.f - ALPHA) * acc1 + ALPHA * hr[32 + lane];
}

// ---------------- log_softmax over 40 classes, warp per row ----------------
// After KHOP=10 iterations (last it=9 odd), the result lives in g_zB.
__global__ __launch_bounds__(256) void logsoftmax_kernel(float* __restrict__ out) {
  int warp = threadIdx.x >> 5, lane = threadIdx.x & 31;
  int row = blockIdx.x * 8 + warp;
  if (row >= Nn) return;
  const float* zr = g_zB + (size_t)row * NCLASS;
  float x0 = zr[lane];
  float x1 = (lane < 8) ? zr[32 + lane] : -1e30f;
  float m = fmaxf(x0, x1);
  #pragma unroll
  for (int off = 16; off > 0; off >>= 1)
    m = fmaxf(m, __shfl_xor_sync(0xffffffffu, m, off));
  float s = expf(x0 - m) + ((lane < 8) ? expf(x1 - m) : 0.f);
  #pragma unroll
  for (int off = 16; off > 0; off >>= 1)
    s += __shfl_xor_sync(0xffffffffu, s, off);
  float ls = logf(s);
  out[(size_t)row * NCLASS + lane] = x0 - m - ls;
  if (lane < 8) out[(size_t)row * NCLASS + 32 + lane] = x1 - m - ls;
}

// ---------------- launch ----------------
extern "C" void kernel_launch(void* const* d_in, const int* in_sizes, int n_in,
                              void* d_out, int out_size) {
  const float* x    = (const float*)d_in[0];
  const int*   esrc = (const int*)  d_in[1];
  const int*   edst = (const int*)  d_in[2];
  const float* ev   = (const float*)d_in[3];
  const float* W1   = (const float*)d_in[4];
  const float* b1   = (const float*)d_in[5];
  const float* W2   = (const float*)d_in[6];
  const float* b2   = (const float*)d_in[7];
  float* out = (float*)d_out;

  dim3 g1(NHID / 128, (Nn + 127) / 128);
  gemm1_relu_kernel<<<g1, 256>>>(x, W1, b1);
  gemm2_kernel<<<(Nn + 47) / 48, 256>>>(W2, b2);

  zero_counts_kernel<<<(Nn + 255) / 256, 256>>>();
  hist_kernel<<<(Ee + 255) / 256, 256>>>(edst);
  scan_kernel<<<1, 1024>>>();
  scatter_kernel<<<(Ee + 255) / 256, 256>>>(esrc, edst, ev);

  for (int it = 0; it < KHOP; it++)
    spmm_kernel<<<(Nn + 7) / 8, 256>>>(it);

  logsoftmax_kernel<<<(Nn + 7) / 8, 256>>>(out);
}

// round 6
// speedup vs baseline: 1.8772x; 1.8772x over previous
#include <cuda_runtime.h>
#include <math.h>
#include <stdint.h>

#define Nn     100000
#define Ee     1600000
#define NFEAT  512
#define NHID   256
#define NCLASS 40
#define KHOP   10
#define ALPHA  0.1f
#define NB     ((Nn + 255) / 256)   // 391 scan blocks

// ---------------- scratch (static __device__ — no allocations allowed) ----------------
__device__ float g_h1[(size_t)Nn * NHID];     // relu(x@W1+b1)   [N,256]
__device__ float g_h [(size_t)Nn * NCLASS];   // h1@W2+b2        [N,40]
__device__ float g_zA[(size_t)Nn * NCLASS];
__device__ float g_zB[(size_t)Nn * NCLASS];
// W1 in mma-pair layout: [(k8*256 + n)*8 + kk*2 + h] = rna_tf32(W1[(k8*8+kk+4h)*256 + n])
__device__ float g_W1p[(size_t)NFEAT * NHID];
__device__ int   g_counts[Nn];
__device__ int   g_rowptr[Nn + 1];
__device__ int   g_cursor[Nn];
__device__ int   g_bsum[NB];
__device__ int   g_boff[NB + 1];
__device__ int   g_csr_src[Ee];
__device__ float g_csr_val[Ee];

// ---------------- helpers (sm_80+ PTX only — NO tcgen05, harness targets plain sm_103) ----------------
__device__ __forceinline__ uint32_t smem_u32(const void* p) {
  uint32_t a;
  asm("{ .reg .u64 t; cvta.to.shared.u64 t, %1; cvt.u32.u64 %0, t; }" : "=r"(a) : "l"(p));
  return a;
}
__device__ __forceinline__ uint32_t rna_tf32_bits(float x) {
  uint32_t u;
  asm("cvt.rna.tf32.f32 %0, %1;" : "=r"(u) : "f"(x));
  return u;
}
__device__ __forceinline__ void cp_async16(uint32_t dst, const void* src, uint32_t srcsz) {
  asm volatile("cp.async.cg.shared.global [%0], [%1], 16, %2;"
               :: "r"(dst), "l"(src), "r"(srcsz) : "memory");
}
__device__ __forceinline__ void mma_tf32(float d[4], const uint32_t a[4], const uint32_t b[2]) {
  asm volatile("mma.sync.aligned.m16n8k8.row.col.f32.tf32.tf32.f32 "
               "{%0,%1,%2,%3}, {%4,%5,%6,%7}, {%8,%9}, {%0,%1,%2,%3};"
               : "+f"(d[0]), "+f"(d[1]), "+f"(d[2]), "+f"(d[3])
               : "r"(a[0]), "r"(a[1]), "r"(a[2]), "r"(a[3]), "r"(b[0]), "r"(b[1]));
}

// ---------------- W1 prep: transpose + tf32 round + mma pair permute ----------------
__global__ void prep_w1_kernel(const float* __restrict__ W1) {
  int o = blockIdx.x * 256 + threadIdx.x;
  if (o < NFEAT * NHID) {
    int inner = o & 7;          // kk*2 + h
    int n     = (o >> 3) & 255;
    int k8    = o >> 11;        // 0..63
    int kk    = inner >> 1, h = inner & 1;
    int k     = k8 * 8 + kk + h * 4;
    g_W1p[o] = __uint_as_float(rna_tf32_bits(W1[(size_t)k * NHID + n]));
  }
}

// ---------------- GEMM1 (mma.sync tf32): h1 = relu(x @ W1 + b1) ----------------
// CTA tile 128x128, BK=32, cp.async double buffer; 8 warps = 4(M) x 2(N), warp tile 32x64.
#define G1_SMEM 65536

__device__ __forceinline__ void g1_load_stage(const float* __restrict__ x, int tileM,
                                              int cColBase, int st, uint32_t dA, uint32_t dB,
                                              int tid) {
  // A: 128 rows x 32 floats, XOR-chunk swizzle; zero-fill OOB rows
  #pragma unroll
  for (int q = 0; q < 4; q++) {
    int c = q * 256 + tid;
    int m = c >> 3, ch = c & 7;
    int row = tileM + m;
    const float* src = x + (size_t)(row < Nn ? row : 0) * NFEAT + st * 32 + ch * 4;
    uint32_t dst = dA + m * 128 + ((ch ^ (m & 7)) << 4);
    cp_async16(dst, src, row < Nn ? 16u : 0u);
  }
  // B: 4 k8-chunks x 128 n x 32B pairs, direct copy (gmem already permuted)
  #pragma unroll
  for (int q = 0; q < 4; q++) {
    int c = q * 256 + tid;
    int k8l = c >> 8, rem = c & 255, n = rem >> 1, half = rem & 1;
    const float* src = g_W1p + ((size_t)((st * 4 + k8l) * 256) + cColBase + n) * 8 + half * 4;
    uint32_t dst = dB + k8l * 4096 + n * 32 + half * 16;
    cp_async16(dst, src, 16u);
  }
  asm volatile("cp.async.commit_group;" ::: "memory");
}

__device__ __forceinline__ void g1_compute_stage(uint32_t aBase, uint32_t bBase,
                                                 int wm, int wn, int g, int tig,
                                                 float acc[2][8][4]) {
  #pragma unroll
  for (int k8l = 0; k8l < 4; k8l++) {
    uint32_t bf[8][2];
    #pragma unroll
    for (int j = 0; j < 8; j++) {
      uint32_t addr = bBase + k8l * 4096 + (wn * 64 + j * 8 + g) * 32 + tig * 8;
      asm volatile("ld.shared.v2.b32 {%0,%1}, [%2];"
                   : "=r"(bf[j][0]), "=r"(bf[j][1]) : "r"(addr));
    }
    uint32_t af[2][4];
    #pragma unroll
    for (int mf = 0; mf < 2; mf++) {
      int r0 = wm * 32 + mf * 16 + g;
      int r1 = r0 + 8;
      #pragma unroll
      for (int h = 0; h < 2; h++) {
        int chunk = k8l * 2 + h;
        uint32_t ad0 = aBase + r0 * 128 + ((chunk ^ (r0 & 7)) << 4) + tig * 4;
        uint32_t ad1 = aBase + r1 * 128 + ((chunk ^ (r1 & 7)) << 4) + tig * 4;
        float f0, f1;
        asm volatile("ld.shared.f32 %0, [%1];" : "=f"(f0) : "r"(ad0));
        asm volatile("ld.shared.f32 %0, [%1];" : "=f"(f1) : "r"(ad1));
        af[mf][h * 2 + 0] = rna_tf32_bits(f0);
        af[mf][h * 2 + 1] = rna_tf32_bits(f1);
      }
    }
    #pragma unroll
    for (int mf = 0; mf < 2; mf++)
      #pragma unroll
      for (int j = 0; j < 8; j++)
        mma_tf32(acc[mf][j], af[mf], bf[j]);
  }
}

__global__ __launch_bounds__(256) void gemm1_mma_kernel(const float* __restrict__ x,
                                                        const float* __restrict__ bias) {
  extern __shared__ char smem[];
  const uint32_t sb = smem_u32(smem);
  const int tid = threadIdx.x, wid = tid >> 5, lane = tid & 31;
  const int g = lane >> 2, tig = lane & 3;
  const int cColBase = blockIdx.x * 128;
  const int tileM    = blockIdx.y * 128;
  const int wm = wid >> 1, wn = wid & 1;
  const uint32_t sA[2] = {sb, sb + 16384u};
  const uint32_t sB[2] = {sb + 32768u, sb + 49152u};

  float acc[2][8][4];
  #pragma unroll
  for (int a = 0; a < 2; a++)
    #pragma unroll
    for (int b = 0; b < 8; b++)
      #pragma unroll
      for (int c = 0; c < 4; c++) acc[a][b][c] = 0.f;

  g1_load_stage(x, tileM, cColBase, 0, sA[0], sB[0], tid);
  g1_load_stage(x, tileM, cColBase, 1, sA[1], sB[1], tid);

  #pragma unroll 1
  for (int st = 0; st < 16; st++) {
    int buf = st & 1;
    if (st < 15) asm volatile("cp.async.wait_group 1;" ::: "memory");
    else         asm volatile("cp.async.wait_group 0;" ::: "memory");
    __syncthreads();
    g1_compute_stage(sA[buf], sB[buf], wm, wn, g, tig, acc);
    __syncthreads();
    if (st + 2 < 16) g1_load_stage(x, tileM, cColBase, st + 2, sA[buf], sB[buf], tid);
  }

  // epilogue: bias + relu + float2 stores straight from C fragments
  #pragma unroll
  for (int j = 0; j < 8; j++) {
    int col = cColBase + wn * 64 + j * 8 + tig * 2;
    float2 bv = *reinterpret_cast<const float2*>(bias + col);
    #pragma unroll
    for (int mf = 0; mf < 2; mf++) {
      int row0 = tileM + wm * 32 + mf * 16 + g;
      int row1 = row0 + 8;
      if (row0 < Nn) {
        float2 o;
        o.x = fmaxf(acc[mf][j][0] + bv.x, 0.f);
        o.y = fmaxf(acc[mf][j][1] + bv.y, 0.f);
        *reinterpret_cast<float2*>(&g_h1[(size_t)row0 * NHID + col]) = o;
      }
      if (row1 < Nn) {
        float2 o;
        o.x = fmaxf(acc[mf][j][2] + bv.x, 0.f);
        o.y = fmaxf(acc[mf][j][3] + bv.y, 0.f);
        *reinterpret_cast<float2*>(&g_h1[(size_t)row1 * NHID + col]) = o;
      }
    }
  }
}

// ---------------- GEMM2: h = h1 @ W2 + b2, [N,256]x[256,40] ----------------
__global__ __launch_bounds__(256) void gemm2_kernel(
    const float* __restrict__ W2, const float* __restrict__ b2)
{
  __shared__ float h1s[48 * 68];
  __shared__ float w2s[64 * NCLASS];
  const int t    = threadIdx.x;
  const int base = blockIdx.x * 48;
  const int cp   = t % 20;
  const int rg   = t / 20;
  float acc[4][2] = {{0.f,0.f},{0.f,0.f},{0.f,0.f},{0.f,0.f}};

  for (int kc = 0; kc < NHID; kc += 64) {
    for (int idx = t; idx < 48 * 16; idx += 256) {
      int r = idx / 16, c4 = idx % 16;
      int row = base + r;
      float4 v = make_float4(0.f, 0.f, 0.f, 0.f);
      if (row < Nn)
        v = *reinterpret_cast<const float4*>(&g_h1[(size_t)row * NHID + kc + c4 * 4]);
      *reinterpret_cast<float4*>(&h1s[r * 68 + c4 * 4]) = v;
    }
    for (int idx = t; idx < 64 * NCLASS; idx += 256)
      w2s[idx] = W2[(size_t)(kc + idx / NCLASS) * NCLASS + idx % NCLASS];
    __syncthreads();
    if (rg < 12) {
      #pragma unroll 8
      for (int k = 0; k < 64; k++) {
        float w0 = w2s[k * NCLASS + cp * 2];
        float w1 = w2s[k * NCLASS + cp * 2 + 1];
        #pragma unroll
        for (int rr = 0; rr < 4; rr++) {
          float hv = h1s[(rg * 4 + rr) * 68 + k];
          acc[rr][0] += hv * w0;
          acc[rr][1] += hv * w1;
        }
      }
    }
    __syncthreads();
  }
  if (rg < 12) {
    float bb0 = b2[cp * 2], bb1 = b2[cp * 2 + 1];
    #pragma unroll
    for (int rr = 0; rr < 4; rr++) {
      int row = base + rg * 4 + rr;
      if (row < Nn) {
        g_h[(size_t)row * NCLASS + cp * 2]     = acc[rr][0] + bb0;
        g_h[(size_t)row * NCLASS + cp * 2 + 1] = acc[rr][1] + bb1;
      }
    }
  }
}

// ---------------- CSR build (by dst) ----------------
__global__ void zero_counts_kernel() {
  int i = blockIdx.x * blockDim.x + threadIdx.x;
  if (i < Nn) g_counts[i] = 0;
}

__global__ void hist_kernel(const int* __restrict__ edst) {
  int e = blockIdx.x * blockDim.x + threadIdx.x;
  if (e < Ee) atomicAdd(&g_counts[edst[e]], 1);
}

// 3-pass scan: per-block exclusive scan -> scan of block sums -> add offsets
__global__ __launch_bounds__(256) void scan1_kernel() {
  __shared__ int sh[256];
  int t = threadIdx.x, i = blockIdx.x * 256 + t;
  int v = (i < Nn) ? g_counts[i] : 0;
  sh[t] = v;
  __syncthreads();
  #pragma unroll
  for (int off = 1; off < 256; off <<= 1) {
    int tv = (t >= off) ? sh[t - off] : 0;
    __syncthreads();
    sh[t] += tv;
    __syncthreads();
  }
  if (i < Nn) g_rowptr[i] = sh[t] - v;
  if (t == 255) g_bsum[blockIdx.x] = sh[255];
}

__global__ __launch_bounds__(512) void scan2_kernel() {
  __shared__ int sh[512];
  int t = threadIdx.x;
  int v = (t < NB) ? g_bsum[t] : 0;
  sh[t] = v;
  __syncthreads();
  #pragma unroll
  for (int off = 1; off < 512; off <<= 1) {
    int tv = (t >= off) ? sh[t - off] : 0;
    __syncthreads();
    sh[t] += tv;
    __syncthreads();
  }
  if (t < NB) g_boff[t] = sh[t] - v;
  if (t == NB - 1) g_boff[NB] = sh[t];
}

__global__ __launch_bounds__(256) void scan3_kernel() {
  int i = blockIdx.x * 256 + threadIdx.x;
  if (i < Nn) {
    int r = g_rowptr[i] + g_boff[blockIdx.x];
    g_rowptr[i] = r;
    g_cursor[i] = r;
  }
  if (i == 0) g_rowptr[Nn] = g_boff[NB];
}

__global__ void scatter_kernel(const int* __restrict__ esrc, const int* __restrict__ edst,
                               const float* __restrict__ eval) {
  int e = blockIdx.x * blockDim.x + threadIdx.x;
  if (e < Ee) {
    int d = edst[e];
    int p = atomicAdd(&g_cursor[d], 1);
    g_csr_src[p] = esrc[e];
    g_csr_val[p] = eval[e];
  }
}

// ---------------- APPNP propagation: z = 0.9 * (A z) + 0.1 * h ----------------
// Warp per dst row; lanes 0..19 each own 2 classes via float2 (one LDG.64 per edge).
__global__ __launch_bounds__(256) void spmm_kernel(int it) {
  const float* zin  = (it == 0) ? g_h : ((it & 1) ? g_zA : g_zB);
  float*       zout = (it & 1) ? g_zB : g_zA;
  int warp = threadIdx.x >> 5, lane = threadIdx.x & 31;
  int row = blockIdx.x * 8 + warp;
  if (row >= Nn) return;
  int s = g_rowptr[row], e = g_rowptr[row + 1];
  float ax = 0.f, ay = 0.f;
  int i = s;
  for (; i + 2 <= e; i += 2) {
    int   s0 = g_csr_src[i],   s1 = g_csr_src[i + 1];
    float v0 = g_csr_val[i],   v1 = g_csr_val[i + 1];
    if (lane < 20) {
      float2 z0 = *reinterpret_cast<const float2*>(zin + (size_t)s0 * NCLASS + lane * 2);
      float2 z1 = *reinterpret_cast<const float2*>(zin + (size_t)s1 * NCLASS + lane * 2);
      ax += v0 * z0.x + v1 * z1.x;
      ay += v0 * z0.y + v1 * z1.y;
    }
  }
  if (i < e) {
    int s0 = g_csr_src[i];
    float v0 = g_csr_val[i];
    if (lane < 20) {
      float2 z0 = *reinterpret_cast<const float2*>(zin + (size_t)s0 * NCLASS + lane * 2);
      ax += v0 * z0.x;
      ay += v0 * z0.y;
    }
  }
  if (lane < 20) {
    float2 h2 = *reinterpret_cast<const float2*>(g_h + (size_t)row * NCLASS + lane * 2);
    float2 o;
    o.x = (1.f - ALPHA) * ax + ALPHA * h2.x;
    o.y = (1.f - ALPHA) * ay + ALPHA * h2.y;
    *reinterpret_cast<float2*>(zout + (size_t)row * NCLASS + lane * 2) = o;
  }
}

// ---------------- log_softmax over 40 classes, warp per row ----------------
__global__ __launch_bounds__(256) void logsoftmax_kernel(float* __restrict__ out) {
  int warp = threadIdx.x >> 5, lane = threadIdx.x & 31;
  int row = blockIdx.x * 8 + warp;
  if (row >= Nn) return;
  const float* zr = g_zB + (size_t)row * NCLASS;
  float x0 = zr[lane];
  float x1 = (lane < 8) ? zr[32 + lane] : -1e30f;
  float m = fmaxf(x0, x1);
  #pragma unroll
  for (int off = 16; off > 0; off >>= 1)
    m = fmaxf(m, __shfl_xor_sync(0xffffffffu, m, off));
  float s = expf(x0 - m) + ((lane < 8) ? expf(x1 - m) : 0.f);
  #pragma unroll
  for (int off = 16; off > 0; off >>= 1)
    s += __shfl_xor_sync(0xffffffffu, s, off);
  float ls = logf(s);
  out[(size_t)row * NCLASS + lane] = x0 - m - ls;
  if (lane < 8) out[(size_t)row * NCLASS + 32 + lane] = x1 - m - ls;
}

// ---------------- launch ----------------
extern "C" void kernel_launch(void* const* d_in, const int* in_sizes, int n_in,
                              void* d_out, int out_size) {
  const float* x    = (const float*)d_in[0];
  const int*   esrc = (const int*)  d_in[1];
  const int*   edst = (const int*)  d_in[2];
  const float* ev   = (const float*)d_in[3];
  const float* W1   = (const float*)d_in[4];
  const float* b1   = (const float*)d_in[5];
  const float* W2   = (const float*)d_in[6];
  const float* b2   = (const float*)d_in[7];
  float* out = (float*)d_out;

  cudaFuncSetAttribute(gemm1_mma_kernel, cudaFuncAttributeMaxDynamicSharedMemorySize, G1_SMEM);

  prep_w1_kernel<<<(NFEAT * NHID + 255) / 256, 256>>>(W1);
  dim3 g1(2, (Nn + 127) / 128);
  gemm1_mma_kernel<<<g1, 256, G1_SMEM>>>(x, b1);
  gemm2_kernel<<<(Nn + 47) / 48, 256>>>(W2, b2);

  zero_counts_kernel<<<(Nn + 255) / 256, 256>>>();
  hist_kernel<<<(Ee + 255) / 256, 256>>>(edst);
  scan1_kernel<<<NB, 256>>>();
  scan2_kernel<<<1, 512>>>();
  scan3_kernel<<<NB, 256>>>();
  scatter_kernel<<<(Ee + 255) / 256, 256>>>(esrc, edst, ev);

  for (int it = 0; it < KHOP; it++)
    spmm_kernel<<<(Nn + 7) / 8, 256>>>(it);

  logsoftmax_kernel<<<(Nn + 7) / 8, 256>>>(out);
}

// round 11
// speedup vs baseline: 1.9408x; 1.0339x over previous
#include <cuda_runtime.h>
#include <cuda_fp16.h>
#include <math.h>
#include <stdint.h>

#define Nn     100000
#define Ee     1600000
#define NFEAT  512
#define NHID   256
#define NCLASS 40
#define KHOP   10
#define ALPHA  0.1f
#define NB     ((Nn + 255) / 256)   // 391 scan blocks

// ---------------- scratch (static __device__ — no allocations allowed) ----------------
__device__ float  g_h1[(size_t)Nn * NHID];      // relu(x@W1+b1)   [N,256] fp32
__device__ __half g_hh [(size_t)Nn * NCLASS];   // h = h1@W2+b2    [N,40]  fp16
__device__ __half g_zhA[(size_t)Nn * NCLASS];   // propagation ping
__device__ __half g_zhB[(size_t)Nn * NCLASS];   // propagation pong
__device__ float  g_zF [(size_t)Nn * NCLASS];   // final z (fp32) for log_softmax
// W1 in mma-pair layout: [(k8*256 + n)*8 + kk*2 + h] = rna_tf32(W1[(k8*8+kk+4h)*256 + n])
__device__ float  g_W1p[(size_t)NFEAT * NHID];
// W2 in mma-pair layout: [(k8*40 + n)*8 + kk*2 + h] = rna_tf32(W2[(k8*8+kk+4h)*40 + n])
__device__ float  g_W2p[(size_t)NHID * NCLASS];
__device__ int    g_counts[Nn];
__device__ int    g_rowptr[Nn + 1];
__device__ int    g_cursor[Nn];
__device__ int    g_bsum[NB];
__device__ int    g_boff[NB + 1];
__device__ int    g_csr_src[Ee];
__device__ float  g_csr_val[Ee];

// ---------------- helpers (sm_80+ PTX only — NO tcgen05, harness targets plain sm_103) ----------------
__device__ __forceinline__ uint32_t smem_u32(const void* p) {
  uint32_t a;
  asm("{ .reg .u64 t; cvta.to.shared.u64 t, %1; cvt.u32.u64 %0, t; }" : "=r"(a) : "l"(p));
  return a;
}
__device__ __forceinline__ uint32_t rna_tf32_bits(float x) {
  uint32_t u;
  asm("cvt.rna.tf32.f32 %0, %1;" : "=r"(u) : "f"(x));
  return u;
}
__device__ __forceinline__ void cp_async16(uint32_t dst, const void* src, uint32_t srcsz) {
  asm volatile("cp.async.cg.shared.global [%0], [%1], 16, %2;"
               :: "r"(dst), "l"(src), "r"(srcsz) : "memory");
}
__device__ __forceinline__ void mma_tf32(float d[4], const uint32_t a[4], const uint32_t b[2]) {
  asm volatile("mma.sync.aligned.m16n8k8.row.col.f32.tf32.tf32.f32 "
               "{%0,%1,%2,%3}, {%4,%5,%6,%7}, {%8,%9}, {%0,%1,%2,%3};"
               : "+f"(d[0]), "+f"(d[1]), "+f"(d[2]), "+f"(d[3])
               : "r"(a[0]), "r"(a[1]), "r"(a[2]), "r"(a[3]), "r"(b[0]), "r"(b[1]));
}

// ---------------- W1/W2 prep: transpose + tf32 round + mma pair permute ----------------
__global__ void prep_w1_kernel(const float* __restrict__ W1) {
  int o = blockIdx.x * 256 + threadIdx.x;
  if (o < NFEAT * NHID) {
    int inner = o & 7;          // kk*2 + h
    int n     = (o >> 3) & 255;
    int k8    = o >> 11;        // 0..63
    int kk    = inner >> 1, h = inner & 1;
    int k     = k8 * 8 + kk + h * 4;
    g_W1p[o] = __uint_as_float(rna_tf32_bits(W1[(size_t)k * NHID + n]));
  }
}

__global__ void prep_w2_kernel(const float* __restrict__ W2) {
  int o = blockIdx.x * 256 + threadIdx.x;
  if (o < NHID * NCLASS) {
    int k8    = o / 320;        // 0..31
    int rem   = o % 320;
    int n     = rem >> 3;       // 0..39
    int inner = rem & 7;
    int kk    = inner >> 1, h = inner & 1;
    int k     = k8 * 8 + kk + h * 4;
    g_W2p[o] = __uint_as_float(rna_tf32_bits(W2[(size_t)k * NCLASS + n]));
  }
}

// ---------------- GEMM1 (mma.sync tf32): h1 = relu(x @ W1 + b1) ----------------
// CTA tile 128x128, BK=32, cp.async double buffer; 8 warps = 4(M) x 2(N), warp tile 32x64.
#define G1_SMEM 65536

__device__ __forceinline__ void g1_load_stage(const float* __restrict__ x, int tileM,
                                              int cColBase, int st, uint32_t dA, uint32_t dB,
                                              int tid) {
  // A: 128 rows x 32 floats, XOR-chunk swizzle; zero-fill OOB rows
  #pragma unroll
  for (int q = 0; q < 4; q++) {
    int c = q * 256 + tid;
    int m = c >> 3, ch = c & 7;
    int row = tileM + m;
    const float* src = x + (size_t)(row < Nn ? row : 0) * NFEAT + st * 32 + ch * 4;
    uint32_t dst = dA + m * 128 + ((ch ^ (m & 7)) << 4);
    cp_async16(dst, src, row < Nn ? 16u : 0u);
  }
  // B: 4 k8-chunks x 128 n x 32B pairs, direct copy (gmem already permuted)
  #pragma unroll
  for (int q = 0; q < 4; q++) {
    int c = q * 256 + tid;
    int k8l = c >> 8, rem = c & 255, n = rem >> 1, half = rem & 1;
    const float* src = g_W1p + ((size_t)((st * 4 + k8l) * 256) + cColBase + n) * 8 + half * 4;
    uint32_t dst = dB + k8l * 4096 + n * 32 + half * 16;
    cp_async16(dst, src, 16u);
  }
  asm volatile("cp.async.commit_group;" ::: "memory");
}

__device__ __forceinline__ void g1_compute_stage(uint32_t aBase, uint32_t bBase,
                                                 int wm, int wn, int g, int tig,
                                                 float acc[2][8][4]) {
  #pragma unroll
  for (int k8l = 0; k8l < 4; k8l++) {
    uint32_t bf[8][2];
    #pragma unroll
    for (int j = 0; j < 8; j++) {
      uint32_t addr = bBase + k8l * 4096 + (wn * 64 + j * 8 + g) * 32 + tig * 8;
      asm volatile("ld.shared.v2.b32 {%0,%1}, [%2];"
                   : "=r"(bf[j][0]), "=r"(bf[j][1]) : "r"(addr));
    }
    uint32_t af[2][4];
    #pragma unroll
    for (int mf = 0; mf < 2; mf++) {
      int r0 = wm * 32 + mf * 16 + g;
      int r1 = r0 + 8;
      #pragma unroll
      for (int h = 0; h < 2; h++) {
        int chunk = k8l * 2 + h;
        uint32_t ad0 = aBase + r0 * 128 + ((chunk ^ (r0 & 7)) << 4) + tig * 4;
        uint32_t ad1 = aBase + r1 * 128 + ((chunk ^ (r1 & 7)) << 4) + tig * 4;
        float f0, f1;
        asm volatile("ld.shared.f32 %0, [%1];" : "=f"(f0) : "r"(ad0));
        asm volatile("ld.shared.f32 %0, [%1];" : "=f"(f1) : "r"(ad1));
        af[mf][h * 2 + 0] = rna_tf32_bits(f0);
        af[mf][h * 2 + 1] = rna_tf32_bits(f1);
      }
    }
    #pragma unroll
    for (int mf = 0; mf < 2; mf++)
      #pragma unroll
      for (int j = 0; j < 8; j++)
        mma_tf32(acc[mf][j], af[mf], bf[j]);
  }
}

__global__ __launch_bounds__(256) void gemm1_mma_kernel(const float* __restrict__ x,
                                                        const float* __restrict__ bias) {
  extern __shared__ char smem[];
  const uint32_t sb = smem_u32(smem);
  const int tid = threadIdx.x, wid = tid >> 5, lane = tid & 31;
  const int g = lane >> 2, tig = lane & 3;
  const int cColBase = blockIdx.x * 128;
  const int tileM    = blockIdx.y * 128;
  const int wm = wid >> 1, wn = wid & 1;
  const uint32_t sA[2] = {sb, sb + 16384u};
  const uint32_t sB[2] = {sb + 32768u, sb + 49152u};

  float acc[2][8][4];
  #pragma unroll
  for (int a = 0; a < 2; a++)
    #pragma unroll
    for (int b = 0; b < 8; b++)
      #pragma unroll
      for (int c = 0; c < 4; c++) acc[a][b][c] = 0.f;

  g1_load_stage(x, tileM, cColBase, 0, sA[0], sB[0], tid);
  g1_load_stage(x, tileM, cColBase, 1, sA[1], sB[1], tid);

  #pragma unroll 1
  for (int st = 0; st < 16; st++) {
    int buf = st & 1;
    if (st < 15) asm volatile("cp.async.wait_group 1;" ::: "memory");
    else         asm volatile("cp.async.wait_group 0;" ::: "memory");
    __syncthreads();
    g1_compute_stage(sA[buf], sB[buf], wm, wn, g, tig, acc);
    __syncthreads();
    if (st + 2 < 16) g1_load_stage(x, tileM, cColBase, st + 2, sA[buf], sB[buf], tid);
  }

  // epilogue: bias + relu + float2 stores straight from C fragments
  #pragma unroll
  for (int j = 0; j < 8; j++) {
    int col = cColBase + wn * 64 + j * 8 + tig * 2;
    float2 bv = *reinterpret_cast<const float2*>(bias + col);
    #pragma unroll
    for (int mf = 0; mf < 2; mf++) {
      int row0 = tileM + wm * 32 + mf * 16 + g;
      int row1 = row0 + 8;
      if (row0 < Nn) {
        float2 o;
        o.x = fmaxf(acc[mf][j][0] + bv.x, 0.f);
        o.y = fmaxf(acc[mf][j][1] + bv.y, 0.f);
        *reinterpret_cast<float2*>(&g_h1[(size_t)row0 * NHID + col]) = o;
      }
      if (row1 < Nn) {
        float2 o;
        o.x = fmaxf(acc[mf][j][2] + bv.x, 0.f);
        o.y = fmaxf(acc[mf][j][3] + bv.y, 0.f);
        *reinterpret_cast<float2*>(&g_h1[(size_t)row1 * NHID + col]) = o;
      }
    }
  }
}

// ---------------- GEMM2 (mma.sync tf32): h = h1 @ W2 + b2 -> fp16 g_hh ----------------
// CTA tile 128x40, BK=32, 8 warps each own 16 rows; warp tile 16x40 (5 n8 fragments).
__global__ __launch_bounds__(256) void gemm2_mma_kernel(const float* __restrict__ b2) {
  __shared__ float sAf[2][4096];   // 128 x 32, XOR-chunk swizzled
  __shared__ float sBf[2][1280];   // 4 k8-chunks x 40 n x 8 pair-floats
  const uint32_t sA[2] = {smem_u32(sAf[0]), smem_u32(sAf[1])};
  const uint32_t sB[2] = {smem_u32(sBf[0]), smem_u32(sBf[1])};
  const int tid = threadIdx.x, wid = tid >> 5, lane = tid & 31;
  const int g = lane >> 2, tig = lane & 3;
  const int tileM = blockIdx.x * 128;

  float acc[5][4];
  #pragma unroll
  for (int j = 0; j < 5; j++)
    #pragma unroll
    for (int c = 0; c < 4; c++) acc[j][c] = 0.f;

  auto load_stage = [&](int st, int buf) {
    #pragma unroll
    for (int q = 0; q < 4; q++) {
      int c = q * 256 + tid;
      int m = c >> 3, ch = c & 7;
      int row = tileM + m;
      const float* src = g_h1 + (size_t)(row < Nn ? row : 0) * NHID + st * 32 + ch * 4;
      uint32_t dst = sA[buf] + m * 128 + ((ch ^ (m & 7)) << 4);
      cp_async16(dst, src, row < Nn ? 16u : 0u);
    }
    #pragma unroll
    for (int q = 0; q < 2; q++) {
      int c = q * 256 + tid;
      if (c < 320) {
        int k8l = c / 80, rem = c % 80, n = rem >> 1, half = rem & 1;
        const float* src = g_W2p + ((size_t)((st * 4 + k8l) * NCLASS) + n) * 8 + half * 4;
        uint32_t dst = sB[buf] + k8l * 1280 + n * 32 + half * 16;
        cp_async16(dst, src, 16u);
      }
    }
    asm volatile("cp.async.commit_group;" ::: "memory");
  };

  load_stage(0, 0);
  load_stage(1, 1);

  #pragma unroll 1
  for (int st = 0; st < 8; st++) {
    int buf = st & 1;
    if (st < 7) asm volatile("cp.async.wait_group 1;" ::: "memory");
    else        asm volatile("cp.async.wait_group 0;" ::: "memory");
    __syncthreads();
    #pragma unroll
    for (int k8l = 0; k8l < 4; k8l++) {
      uint32_t bf[5][2];
      #pragma unroll
      for (int j = 0; j < 5; j++) {
        uint32_t addr = sB[buf] + k8l * 1280 + (j * 8 + g) * 32 + tig * 8;
        asm volatile("ld.shared.v2.b32 {%0,%1}, [%2];"
                     : "=r"(bf[j][0]), "=r"(bf[j][1]) : "r"(addr));
      }
      uint32_t af[4];
      int r0 = wid * 16 + g, r1 = r0 + 8;
      #pragma unroll
      for (int h = 0; h < 2; h++) {
        int chunk = k8l * 2 + h;
        uint32_t ad0 = sA[buf] + r0 * 128 + ((chunk ^ (r0 & 7)) << 4) + tig * 4;
        uint32_t ad1 = sA[buf] + r1 * 128 + ((chunk ^ (r1 & 7)) << 4) + tig * 4;
        float f0, f1;
        asm volatile("ld.shared.f32 %0, [%1];" : "=f"(f0) : "r"(ad0));
        asm volatile("ld.shared.f32 %0, [%1];" : "=f"(f1) : "r"(ad1));
        af[h * 2 + 0] = rna_tf32_bits(f0);
        af[h * 2 + 1] = rna_tf32_bits(f1);
      }
      #pragma unroll
      for (int j = 0; j < 5; j++) mma_tf32(acc[j], af, bf[j]);
    }
    __syncthreads();
    if (st + 2 < 8) load_stage(st + 2, buf);
  }

  // epilogue: + b2, emit fp16 half2
  #pragma unroll
  for (int j = 0; j < 5; j++) {
    int col = j * 8 + tig * 2;
    float2 bv = *reinterpret_cast<const float2*>(b2 + col);
    int row0 = tileM + wid * 16 + g, row1 = row0 + 8;
    if (row0 < Nn)
      *reinterpret_cast<__half2*>(&g_hh[(size_t)row0 * NCLASS + col]) =
          __floats2half2_rn(acc[j][0] + bv.x, acc[j][1] + bv.y);
    if (row1 < Nn)
      *reinterpret_cast<__half2*>(&g_hh[(size_t)row1 * NCLASS + col]) =
          __floats2half2_rn(acc[j][2] + bv.x, acc[j][3] + bv.y);
  }
}

// ---------------- CSR build (by dst) ----------------
__global__ void zero_counts_kernel() {
  int i = blockIdx.x * blockDim.x + threadIdx.x;
  if (i < Nn) g_counts[i] = 0;
}

__global__ void hist_kernel(const int* __restrict__ edst) {
  int e = blockIdx.x * blockDim.x + threadIdx.x;
  if (e < Ee) atomicAdd(&g_counts[edst[e]], 1);
}

// 3-pass scan: per-block exclusive scan -> scan of block sums -> add offsets
__global__ __launch_bounds__(256) void scan1_kernel() {
  __shared__ int sh[256];
  int t = threadIdx.x, i = blockIdx.x * 256 + t;
  int v = (i < Nn) ? g_counts[i] : 0;
  sh[t] = v;
  __syncthreads();
  #pragma unroll
  for (int off = 1; off < 256; off <<= 1) {
    int tv = (t >= off) ? sh[t - off] : 0;
    __syncthreads();
    sh[t] += tv;
    __syncthreads();
  }
  if (i < Nn) g_rowptr[i] = sh[t] - v;
  if (t == 255) g_bsum[blockIdx.x] = sh[255];
}

__global__ __launch_bounds__(512) void scan2_kernel() {
  __shared__ int sh[512];
  int t = threadIdx.x;
  int v = (t < NB) ? g_bsum[t] : 0;
  sh[t] = v;
  __syncthreads();
  #pragma unroll
  for (int off = 1; off < 512; off <<= 1) {
    int tv = (t >= off) ? sh[t - off] : 0;
    __syncthreads();
    sh[t] += tv;
    __syncthreads();
  }
  if (t < NB) g_boff[t] = sh[t] - v;
  if (t == NB - 1) g_boff[NB] = sh[t];
}

__global__ __launch_bounds__(256) void scan3_kernel() {
  int i = blockIdx.x * 256 + threadIdx.x;
  if (i < Nn) {
    int r = g_rowptr[i] + g_boff[blockIdx.x];
    g_rowptr[i] = r;
    g_cursor[i] = r;
  }
  if (i == 0) g_rowptr[Nn] = g_boff[NB];
}

__global__ void scatter_kernel(const int* __restrict__ esrc, const int* __restrict__ edst,
                               const float* __restrict__ eval) {
  int e = blockIdx.x * blockDim.x + threadIdx.x;
  if (e < Ee) {
    int d = edst[e];
    int p = atomicAdd(&g_cursor[d], 1);
    g_csr_src[p] = esrc[e];
    g_csr_val[p] = eval[e];
  }
}

// ---------------- APPNP propagation: z = 0.9 * (A z) + 0.1 * h  (z in fp16) ----------------
// Warp per dst row; lanes 0..19 each own 2 classes via half2 (one LDG.32 per edge per lane).
// Last iteration writes fp32 to g_zF so log_softmax sees no extra rounding.
__global__ __launch_bounds__(256) void spmm_kernel(int it) {
  const __half* zin  = (it == 0) ? g_hh : ((it & 1) ? g_zhA : g_zhB);
  __half*       zout = (it & 1) ? g_zhB : g_zhA;
  int warp = threadIdx.x >> 5, lane = threadIdx.x & 31;
  int row = blockIdx.x * 8 + warp;
  if (row >= Nn) return;
  int s = g_rowptr[row], e = g_rowptr[row + 1];
  float ax = 0.f, ay = 0.f;
  int i = s;
  for (; i + 2 <= e; i += 2) {
    int   s0 = g_csr_src[i],   s1 = g_csr_src[i + 1];
    float v0 = g_csr_val[i],   v1 = g_csr_val[i + 1];
    if (lane < 20) {
      float2 z0 = __half22float2(*reinterpret_cast<const __half2*>(zin + (size_t)s0 * NCLASS + lane * 2));
      float2 z1 = __half22float2(*reinterpret_cast<const __half2*>(zin + (size_t)s1 * NCLASS + lane * 2));
      ax += v0 * z0.x + v1 * z1.x;
      ay += v0 * z0.y + v1 * z1.y;
    }
  }
  if (i < e) {
    int s0 = g_csr_src[i];
    float v0 = g_csr_val[i];
    if (lane < 20) {
      float2 z0 = __half22float2(*reinterpret_cast<const __half2*>(zin + (size_t)s0 * NCLASS + lane * 2));
      ax += v0 * z0.x;
      ay += v0 * z0.y;
    }
  }
  if (lane < 20) {
    float2 hf = __half22float2(*reinterpret_cast<const __half2*>(g_hh + (size_t)row * NCLASS + lane * 2));
    float ox = (1.f - ALPHA) * ax + ALPHA * hf.x;
    float oy = (1.f - ALPHA) * ay + ALPHA * hf.y;
    if (it == KHOP - 1) {
      *reinterpret_cast<float2*>(g_zF + (size_t)row * NCLASS + lane * 2) = make_float2(ox, oy);
    } else {
      *reinterpret_cast<__half2*>(zout + (size_t)row * NCLASS + lane * 2) = __floats2half2_rn(ox, oy);
    }
  }
}

// ---------------- log_softmax over 40 classes, warp per row ----------------
__global__ __launch_bounds__(256) void logsoftmax_kernel(float* __restrict__ out) {
  int warp = threadIdx.x >> 5, lane = threadIdx.x & 31;
  int row = blockIdx.x * 8 + warp;
  if (row >= Nn) return;
  const float* zr = g_zF + (size_t)row * NCLASS;
  float x0 = zr[lane];
  float x1 = (lane < 8) ? zr[32 + lane] : -1e30f;
  float m = fmaxf(x0, x1);
  #pragma unroll
  for (int off = 16; off > 0; off >>= 1)
    m = fmaxf(m, __shfl_xor_sync(0xffffffffu, m, off));
  float s = expf(x0 - m) + ((lane < 8) ? expf(x1 - m) : 0.f);
  #pragma unroll
  for (int off = 16; off > 0; off >>= 1)
    s += __shfl_xor_sync(0xffffffffu, s, off);
  float ls = logf(s);
  out[(size_t)row * NCLASS + lane] = x0 - m - ls;
  if (lane < 8) out[(size_t)row * NCLASS + 32 + lane] = x1 - m - ls;
}

// ---------------- launch ----------------
extern "C" void kernel_launch(void* const* d_in, const int* in_sizes, int n_in,
                              void* d_out, int out_size) {
  const float* x    = (const float*)d_in[0];
  const int*   esrc = (const int*)  d_in[1];
  const int*   edst = (const int*)  d_in[2];
  const float* ev   = (const float*)d_in[3];
  const float* W1   = (const float*)d_in[4];
  const float* b1   = (const float*)d_in[5];
  const float* W2   = (const float*)d_in[6];
  const float* b2   = (const float*)d_in[7];
  float* out = (float*)d_out;

  cudaFuncSetAttribute(gemm1_mma_kernel, cudaFuncAttributeMaxDynamicSharedMemorySize, G1_SMEM);

  prep_w1_kernel<<<(NFEAT * NHID + 255) / 256, 256>>>(W1);
  prep_w2_kernel<<<(NHID * NCLASS + 255) / 256, 256>>>(W2);
  dim3 g1(2, (Nn + 127) / 128);
  gemm1_mma_kernel<<<g1, 256, G1_SMEM>>>(x, b1);
  gemm2_mma_kernel<<<(Nn + 127) / 128, 256>>>(b2);

  zero_counts_kernel<<<(Nn + 255) / 256, 256>>>();
  hist_kernel<<<(Ee + 255) / 256, 256>>>(edst);
  scan1_kernel<<<NB, 256>>>();
  scan2_kernel<<<1, 512>>>();
  scan3_kernel<<<NB, 256>>>();
  scatter_kernel<<<(Ee + 255) / 256, 256>>>(esrc, edst, ev);

  for (int it = 0; it < KHOP; it++)
    spmm_kernel<<<(Nn + 7) / 8, 256>>>(it);

  logsoftmax_kernel<<<(Nn + 7) / 8, 256>>>(out);
}

// round 15
// speedup vs baseline: 2.2504x; 1.1595x over previous
#include <cuda_runtime.h>
#include <cuda_fp16.h>
#include <math.h>
#include <stdint.h>

#define Nn     100000
#define Ee     1600000
#define NFEAT  512
#define NHID   256
#define NCLASS 40
#define KHOP   10
#define ALPHA  0.1f
#define NB     ((Nn + 255) / 256)   // 391 scan blocks

// ---------------- scratch (static __device__ — no allocations allowed) ----------------
__device__ float  g_h1[(size_t)Nn * NHID];      // relu(x@W1+b1)   [N,256] fp32
__device__ __half g_hh [(size_t)Nn * NCLASS];   // h = h1@W2+b2    [N,40]  fp16
__device__ __half g_zhA[(size_t)Nn * NCLASS];   // propagation ping
__device__ __half g_zhB[(size_t)Nn * NCLASS];   // propagation pong
__device__ float  g_zF [(size_t)Nn * NCLASS];   // final z (fp32) for log_softmax
// W1 in mma-pair layout: [(k8*256 + n)*8 + kk*2 + h] = rna_tf32(W1[(k8*8+kk+4h)*256 + n])
__device__ float  g_W1p[(size_t)NFEAT * NHID];
// W2 in mma-pair layout: [(k8*40 + n)*8 + kk*2 + h] = rna_tf32(W2[(k8*8+kk+4h)*40 + n])
__device__ float  g_W2p[(size_t)NHID * NCLASS];
__device__ int    g_counts[Nn];
__device__ int    g_rowptr[Nn + 1];
__device__ int    g_cursor[Nn];
__device__ int    g_bsum[NB];
__device__ int    g_boff[NB + 1];
__device__ int2   g_csr[Ee];                    // {src, __float_as_int(val)}

// ---------------- helpers (sm_80+ PTX only — NO tcgen05, harness targets plain sm_103) ----------------
__device__ __forceinline__ uint32_t smem_u32(const void* p) {
  uint32_t a;
  asm("{ .reg .u64 t; cvta.to.shared.u64 t, %1; cvt.u32.u64 %0, t; }" : "=r"(a) : "l"(p));
  return a;
}
__device__ __forceinline__ uint32_t rna_tf32_bits(float x) {
  uint32_t u;
  asm("cvt.rna.tf32.f32 %0, %1;" : "=r"(u) : "f"(x));
  return u;
}
__device__ __forceinline__ void cp_async16(uint32_t dst, const void* src, uint32_t srcsz) {
  asm volatile("cp.async.cg.shared.global [%0], [%1], 16, %2;"
               :: "r"(dst), "l"(src), "r"(srcsz) : "memory");
}
__device__ __forceinline__ void mma_tf32(float d[4], const uint32_t a[4], const uint32_t b[2]) {
  asm volatile("mma.sync.aligned.m16n8k8.row.col.f32.tf32.tf32.f32 "
               "{%0,%1,%2,%3}, {%4,%5,%6,%7}, {%8,%9}, {%0,%1,%2,%3};"
               : "+f"(d[0]), "+f"(d[1]), "+f"(d[2]), "+f"(d[3])
               : "r"(a[0]), "r"(a[1]), "r"(a[2]), "r"(a[3]), "r"(b[0]), "r"(b[1]));
}

// ---------------- W1/W2 prep: transpose + tf32 round + mma pair permute ----------------
__global__ void prep_w1_kernel(const float* __restrict__ W1) {
  int o = blockIdx.x * 256 + threadIdx.x;
  if (o < NFEAT * NHID) {
    int inner = o & 7;          // kk*2 + h
    int n     = (o >> 3) & 255;
    int k8    = o >> 11;        // 0..63
    int kk    = inner >> 1, h = inner & 1;
    int k     = k8 * 8 + kk + h * 4;
    g_W1p[o] = __uint_as_float(rna_tf32_bits(W1[(size_t)k * NHID + n]));
  }
}

__global__ void prep_w2_kernel(const float* __restrict__ W2) {
  int o = blockIdx.x * 256 + threadIdx.x;
  if (o < NHID * NCLASS) {
    int k8    = o / 320;        // 0..31
    int rem   = o % 320;
    int n     = rem >> 3;       // 0..39
    int inner = rem & 7;
    int kk    = inner >> 1, h = inner & 1;
    int k     = k8 * 8 + kk + h * 4;
    g_W2p[o] = __uint_as_float(rna_tf32_bits(W2[(size_t)k * NCLASS + n]));
  }
}

// ---------------- GEMM1 (mma.sync tf32): h1 = relu(x @ W1 + b1) ----------------
// CTA tile 128x128, BK=32, cp.async double buffer; 8 warps = 4(M) x 2(N), warp tile 32x64.
#define G1_SMEM 65536

__device__ __forceinline__ void g1_load_stage(const float* __restrict__ x, int tileM,
                                              int cColBase, int st, uint32_t dA, uint32_t dB,
                                              int tid) {
  // A: 128 rows x 32 floats, XOR-chunk swizzle; zero-fill OOB rows
  #pragma unroll
  for (int q = 0; q < 4; q++) {
    int c = q * 256 + tid;
    int m = c >> 3, ch = c & 7;
    int row = tileM + m;
    const float* src = x + (size_t)(row < Nn ? row : 0) * NFEAT + st * 32 + ch * 4;
    uint32_t dst = dA + m * 128 + ((ch ^ (m & 7)) << 4);
    cp_async16(dst, src, row < Nn ? 16u : 0u);
  }
  // B: 4 k8-chunks x 128 n x 32B pairs, direct copy (gmem already permuted)
  #pragma unroll
  for (int q = 0; q < 4; q++) {
    int c = q * 256 + tid;
    int k8l = c >> 8, rem = c & 255, n = rem >> 1, half = rem & 1;
    const float* src = g_W1p + ((size_t)((st * 4 + k8l) * 256) + cColBase + n) * 8 + half * 4;
    uint32_t dst = dB + k8l * 4096 + n * 32 + half * 16;
    cp_async16(dst, src, 16u);
  }
  asm volatile("cp.async.commit_group;" ::: "memory");
}

__device__ __forceinline__ void g1_compute_stage(uint32_t aBase, uint32_t bBase,
                                                 int wm, int wn, int g, int tig,
                                                 float acc[2][8][4]) {
  #pragma unroll
  for (int k8l = 0; k8l < 4; k8l++) {
    uint32_t bf[8][2];
    #pragma unroll
    for (int j = 0; j < 8; j++) {
      uint32_t addr = bBase + k8l * 4096 + (wn * 64 + j * 8 + g) * 32 + tig * 8;
      asm volatile("ld.shared.v2.b32 {%0,%1}, [%2];"
                   : "=r"(bf[j][0]), "=r"(bf[j][1]) : "r"(addr));
    }
    uint32_t af[2][4];
    #pragma unroll
    for (int mf = 0; mf < 2; mf++) {
      int r0 = wm * 32 + mf * 16 + g;
      int r1 = r0 + 8;
      #pragma unroll
      for (int h = 0; h < 2; h++) {
        int chunk = k8l * 2 + h;
        uint32_t ad0 = aBase + r0 * 128 + ((chunk ^ (r0 & 7)) << 4) + tig * 4;
        uint32_t ad1 = aBase + r1 * 128 + ((chunk ^ (r1 & 7)) << 4) + tig * 4;
        float f0, f1;
        asm volatile("ld.shared.f32 %0, [%1];" : "=f"(f0) : "r"(ad0));
        asm volatile("ld.shared.f32 %0, [%1];" : "=f"(f1) : "r"(ad1));
        af[mf][h * 2 + 0] = rna_tf32_bits(f0);
        af[mf][h * 2 + 1] = rna_tf32_bits(f1);
      }
    }
    #pragma unroll
    for (int mf = 0; mf < 2; mf++)
      #pragma unroll
      for (int j = 0; j < 8; j++)
        mma_tf32(acc[mf][j], af[mf], bf[j]);
  }
}

__global__ __launch_bounds__(256) void gemm1_mma_kernel(const float* __restrict__ x,
                                                        const float* __restrict__ bias) {
  extern __shared__ char smem[];
  const uint32_t sb = smem_u32(smem);
  const int tid = threadIdx.x, wid = tid >> 5, lane = tid & 31;
  const int g = lane >> 2, tig = lane & 3;
  const int cColBase = blockIdx.x * 128;
  const int tileM    = blockIdx.y * 128;
  const int wm = wid >> 1, wn = wid & 1;
  const uint32_t sA[2] = {sb, sb + 16384u};
  const uint32_t sB[2] = {sb + 32768u, sb + 49152u};

  float acc[2][8][4];
  #pragma unroll
  for (int a = 0; a < 2; a++)
    #pragma unroll
    for (int b = 0; b < 8; b++)
      #pragma unroll
      for (int c = 0; c < 4; c++) acc[a][b][c] = 0.f;

  g1_load_stage(x, tileM, cColBase, 0, sA[0], sB[0], tid);
  g1_load_stage(x, tileM, cColBase, 1, sA[1], sB[1], tid);

  #pragma unroll 1
  for (int st = 0; st < 16; st++) {
    int buf = st & 1;
    if (st < 15) asm volatile("cp.async.wait_group 1;" ::: "memory");
    else         asm volatile("cp.async.wait_group 0;" ::: "memory");
    __syncthreads();
    g1_compute_stage(sA[buf], sB[buf], wm, wn, g, tig, acc);
    __syncthreads();
    if (st + 2 < 16) g1_load_stage(x, tileM, cColBase, st + 2, sA[buf], sB[buf], tid);
  }

  // epilogue: bias + relu + float2 stores straight from C fragments
  #pragma unroll
  for (int j = 0; j < 8; j++) {
    int col = cColBase + wn * 64 + j * 8 + tig * 2;
    float2 bv = *reinterpret_cast<const float2*>(bias + col);
    #pragma unroll
    for (int mf = 0; mf < 2; mf++) {
      int row0 = tileM + wm * 32 + mf * 16 + g;
      int row1 = row0 + 8;
      if (row0 < Nn) {
        float2 o;
        o.x = fmaxf(acc[mf][j][0] + bv.x, 0.f);
        o.y = fmaxf(acc[mf][j][1] + bv.y, 0.f);
        *reinterpret_cast<float2*>(&g_h1[(size_t)row0 * NHID + col]) = o;
      }
      if (row1 < Nn) {
        float2 o;
        o.x = fmaxf(acc[mf][j][2] + bv.x, 0.f);
        o.y = fmaxf(acc[mf][j][3] + bv.y, 0.f);
        *reinterpret_cast<float2*>(&g_h1[(size_t)row1 * NHID + col]) = o;
      }
    }
  }
}

// ---------------- GEMM2 (mma.sync tf32): h = h1 @ W2 + b2 -> fp16 g_hh ----------------
// CTA tile 128x40, BK=32, 8 warps each own 16 rows; warp tile 16x40 (5 n8 fragments).
__global__ __launch_bounds__(256) void gemm2_mma_kernel(const float* __restrict__ b2) {
  __shared__ float sAf[2][4096];   // 128 x 32, XOR-chunk swizzled
  __shared__ float sBf[2][1280];   // 4 k8-chunks x 40 n x 8 pair-floats
  const uint32_t sA[2] = {smem_u32(sAf[0]), smem_u32(sAf[1])};
  const uint32_t sB[2] = {smem_u32(sBf[0]), smem_u32(sBf[1])};
  const int tid = threadIdx.x, wid = tid >> 5, lane = tid & 31;
  const int g = lane >> 2, tig = lane & 3;
  const int tileM = blockIdx.x * 128;

  float acc[5][4];
  #pragma unroll
  for (int j = 0; j < 5; j++)
    #pragma unroll
    for (int c = 0; c < 4; c++) acc[j][c] = 0.f;

  auto load_stage = [&](int st, int buf) {
    #pragma unroll
    for (int q = 0; q < 4; q++) {
      int c = q * 256 + tid;
      int m = c >> 3, ch = c & 7;
      int row = tileM + m;
      const float* src = g_h1 + (size_t)(row < Nn ? row : 0) * NHID + st * 32 + ch * 4;
      uint32_t dst = sA[buf] + m * 128 + ((ch ^ (m & 7)) << 4);
      cp_async16(dst, src, row < Nn ? 16u : 0u);
    }
    #pragma unroll
    for (int q = 0; q < 2; q++) {
      int c = q * 256 + tid;
      if (c < 320) {
        int k8l = c / 80, rem = c % 80, n = rem >> 1, half = rem & 1;
        const float* src = g_W2p + ((size_t)((st * 4 + k8l) * NCLASS) + n) * 8 + half * 4;
        uint32_t dst = sB[buf] + k8l * 1280 + n * 32 + half * 16;
        cp_async16(dst, src, 16u);
      }
    }
    asm volatile("cp.async.commit_group;" ::: "memory");
  };

  load_stage(0, 0);
  load_stage(1, 1);

  #pragma unroll 1
  for (int st = 0; st < 8; st++) {
    int buf = st & 1;
    if (st < 7) asm volatile("cp.async.wait_group 1;" ::: "memory");
    else        asm volatile("cp.async.wait_group 0;" ::: "memory");
    __syncthreads();
    #pragma unroll
    for (int k8l = 0; k8l < 4; k8l++) {
      uint32_t bf[5][2];
      #pragma unroll
      for (int j = 0; j < 5; j++) {
        uint32_t addr = sB[buf] + k8l * 1280 + (j * 8 + g) * 32 + tig * 8;
        asm volatile("ld.shared.v2.b32 {%0,%1}, [%2];"
                     : "=r"(bf[j][0]), "=r"(bf[j][1]) : "r"(addr));
      }
      uint32_t af[4];
      int r0 = wid * 16 + g, r1 = r0 + 8;
      #pragma unroll
      for (int h = 0; h < 2; h++) {
        int chunk = k8l * 2 + h;
        uint32_t ad0 = sA[buf] + r0 * 128 + ((chunk ^ (r0 & 7)) << 4) + tig * 4;
        uint32_t ad1 = sA[buf] + r1 * 128 + ((chunk ^ (r1 & 7)) << 4) + tig * 4;
        float f0, f1;
        asm volatile("ld.shared.f32 %0, [%1];" : "=f"(f0) : "r"(ad0));
        asm volatile("ld.shared.f32 %0, [%1];" : "=f"(f1) : "r"(ad1));
        af[h * 2 + 0] = rna_tf32_bits(f0);
        af[h * 2 + 1] = rna_tf32_bits(f1);
      }
      #pragma unroll
      for (int j = 0; j < 5; j++) mma_tf32(acc[j], af, bf[j]);
    }
    __syncthreads();
    if (st + 2 < 8) load_stage(st + 2, buf);
  }

  // epilogue: + b2, emit fp16 half2
  #pragma unroll
  for (int j = 0; j < 5; j++) {
    int col = j * 8 + tig * 2;
    float2 bv = *reinterpret_cast<const float2*>(b2 + col);
    int row0 = tileM + wid * 16 + g, row1 = row0 + 8;
    if (row0 < Nn)
      *reinterpret_cast<__half2*>(&g_hh[(size_t)row0 * NCLASS + col]) =
          __floats2half2_rn(acc[j][0] + bv.x, acc[j][1] + bv.y);
    if (row1 < Nn)
      *reinterpret_cast<__half2*>(&g_hh[(size_t)row1 * NCLASS + col]) =
          __floats2half2_rn(acc[j][2] + bv.x, acc[j][3] + bv.y);
  }
}

// ---------------- CSR build (by dst) ----------------
__global__ void zero_counts_kernel() {
  int i = blockIdx.x * blockDim.x + threadIdx.x;
  if (i < Nn) g_counts[i] = 0;
}

__global__ void hist_kernel(const int* __restrict__ edst) {
  int e = blockIdx.x * blockDim.x + threadIdx.x;
  if (e < Ee) atomicAdd(&g_counts[edst[e]], 1);
}

__global__ __launch_bounds__(256) void scan1_kernel() {
  __shared__ int sh[256];
  int t = threadIdx.x, i = blockIdx.x * 256 + t;
  int v = (i < Nn) ? g_counts[i] : 0;
  sh[t] = v;
  __syncthreads();
  #pragma unroll
  for (int off = 1; off < 256; off <<= 1) {
    int tv = (t >= off) ? sh[t - off] : 0;
    __syncthreads();
    sh[t] += tv;
    __syncthreads();
  }
  if (i < Nn) g_rowptr[i] = sh[t] - v;
  if (t == 255) g_bsum[blockIdx.x] = sh[255];
}

__global__ __launch_bounds__(512) void scan2_kernel() {
  __shared__ int sh[512];
  int t = threadIdx.x;
  int v = (t < NB) ? g_bsum[t] : 0;
  sh[t] = v;
  __syncthreads();
  #pragma unroll
  for (int off = 1; off < 512; off <<= 1) {
    int tv = (t >= off) ? sh[t - off] : 0;
    __syncthreads();
    sh[t] += tv;
    __syncthreads();
  }
  if (t < NB) g_boff[t] = sh[t] - v;
  if (t == NB - 1) g_boff[NB] = sh[t];
}

__global__ __launch_bounds__(256) void scan3_kernel() {
  int i = blockIdx.x * 256 + threadIdx.x;
  if (i < Nn) {
    int r = g_rowptr[i] + g_boff[blockIdx.x];
    g_rowptr[i] = r;
    g_cursor[i] = r;
  }
  if (i == 0) g_rowptr[Nn] = g_boff[NB];
}

__global__ void scatter_kernel(const int* __restrict__ esrc, const int* __restrict__ edst,
                               const float* __restrict__ eval) {
  int e = blockIdx.x * blockDim.x + threadIdx.x;
  if (e < Ee) {
    int d = edst[e];
    int p = atomicAdd(&g_cursor[d], 1);
    g_csr[p] = make_int2(esrc[e], __float_as_int(eval[e]));
  }
}

// ---------------- APPNP propagation: z = 0.9 * (A z) + 0.1 * h  (z fp16) ----------------
// Warp per dst row, 3 edge-groups x 10 lanes; each lane gathers 4 classes (uint2).
// Last iteration writes fp32 to g_zF.
__global__ __launch_bounds__(256) void spmm_kernel(int it) {
  const __half* zin  = (it == 0) ? g_hh : ((it & 1) ? g_zhA : g_zhB);
  __half*       zout = (it & 1) ? g_zhB : g_zhA;
  int warp = threadIdx.x >> 5, lane = threadIdx.x & 31;
  int row = blockIdx.x * 8 + warp;
  if (row >= Nn) return;
  int s = g_rowptr[row], e = g_rowptr[row + 1];
  int grp = lane / 10, li = lane % 10;      // grp 3 = lanes 30,31 inactive
  bool act = grp < 3;
  float a0 = 0.f, a1 = 0.f, a2 = 0.f, a3 = 0.f;
  int i = s;
  for (; i + 3 <= e; i += 3) {
    if (act) {
      int2 pv = g_csr[i + grp];
      float v = __int_as_float(pv.y);
      uint2 zb = *reinterpret_cast<const uint2*>(zin + (size_t)pv.x * NCLASS + li * 4);
      float2 f0 = __half22float2(*reinterpret_cast<__half2*>(&zb.x));
      float2 f1 = __half22float2(*reinterpret_cast<__half2*>(&zb.y));
      a0 += v * f0.x; a1 += v * f0.y; a2 += v * f1.x; a3 += v * f1.y;
    }
  }
  if (act && i + grp < e) {
    int2 pv = g_csr[i + grp];
    float v = __int_as_float(pv.y);
    uint2 zb = *reinterpret_cast<const uint2*>(zin + (size_t)pv.x * NCLASS + li * 4);
    float2 f0 = __half22float2(*reinterpret_cast<__half2*>(&zb.x));
    float2 f1 = __half22float2(*reinterpret_cast<__half2*>(&zb.y));
    a0 += v * f0.x; a1 += v * f0.y; a2 += v * f1.x; a3 += v * f1.y;
  }
  // cross-group reduction: lanes 0..9 gather partials from +10, +20
  float t0 = __shfl_sync(0xffffffffu, a0, lane + 10), u0 = __shfl_sync(0xffffffffu, a0, lane + 20);
  float t1 = __shfl_sync(0xffffffffu, a1, lane + 10), u1 = __shfl_sync(0xffffffffu, a1, lane + 20);
  float t2 = __shfl_sync(0xffffffffu, a2, lane + 10), u2 = __shfl_sync(0xffffffffu, a2, lane + 20);
  float t3 = __shfl_sync(0xffffffffu, a3, lane + 10), u3 = __shfl_sync(0xffffffffu, a3, lane + 20);
  a0 += t0 + u0; a1 += t1 + u1; a2 += t2 + u2; a3 += t3 + u3;

  if (lane < 10) {
    uint2 hb = *reinterpret_cast<const uint2*>(g_hh + (size_t)row * NCLASS + lane * 4);
    float2 h0 = __half22float2(*reinterpret_cast<__half2*>(&hb.x));
    float2 h1 = __half22float2(*reinterpret_cast<__half2*>(&hb.y));
    float o0 = (1.f - ALPHA) * a0 + ALPHA * h0.x;
    float o1 = (1.f - ALPHA) * a1 + ALPHA * h0.y;
    float o2 = (1.f - ALPHA) * a2 + ALPHA * h1.x;
    float o3 = (1.f - ALPHA) * a3 + ALPHA * h1.y;
    if (it == KHOP - 1) {
      *reinterpret_cast<float4*>(g_zF + (size_t)row * NCLASS + lane * 4) =
          make_float4(o0, o1, o2, o3);
    } else {
      uint2 ob;
      __half2 olo = __floats2half2_rn(o0, o1), ohi = __floats2half2_rn(o2, o3);
      ob.x = *reinterpret_cast<uint32_t*>(&olo);
      ob.y = *reinterpret_cast<uint32_t*>(&ohi);
      *reinterpret_cast<uint2*>(zout + (size_t)row * NCLASS + lane * 4) = ob;
    }
  }
}

// ---------------- log_softmax over 40 classes, warp per row ----------------
__global__ __launch_bounds__(256) void logsoftmax_kernel(float* __restrict__ out) {
  int warp = threadIdx.x >> 5, lane = threadIdx.x & 31;
  int row = blockIdx.x * 8 + warp;
  if (row >= Nn) return;
  const float* zr = g_zF + (size_t)row * NCLASS;
  float x0 = zr[lane];
  float x1 = (lane < 8) ? zr[32 + lane] : -1e30f;
  float m = fmaxf(x0, x1);
  #pragma unroll
  for (int off = 16; off > 0; off >>= 1)
    m = fmaxf(m, __shfl_xor_sync(0xffffffffu, m, off));
  float s = expf(x0 - m) + ((lane < 8) ? expf(x1 - m) : 0.f);
  #pragma unroll
  for (int off = 16; off > 0; off >>= 1)
    s += __shfl_xor_sync(0xffffffffu, s, off);
  float ls = logf(s);
  out[(size_t)row * NCLASS + lane] = x0 - m - ls;
  if (lane < 8) out[(size_t)row * NCLASS + 32 + lane] = x1 - m - ls;
}

// ---------------- launch ----------------
extern "C" void kernel_launch(void* const* d_in, const int* in_sizes, int n_in,
                              void* d_out, int out_size) {
  const float* x    = (const float*)d_in[0];
  const int*   esrc = (const int*)  d_in[1];
  const int*   edst = (const int*)  d_in[2];
  const float* ev   = (const float*)d_in[3];
  const float* W1   = (const float*)d_in[4];
  const float* b1   = (const float*)d_in[5];
  const float* W2   = (const float*)d_in[6];
  const float* b2   = (const float*)d_in[7];
  float* out = (float*)d_out;

  cudaFuncSetAttribute(gemm1_mma_kernel, cudaFuncAttributeMaxDynamicSharedMemorySize, G1_SMEM);

  prep_w1_kernel<<<(NFEAT * NHID + 255) / 256, 256>>>(W1);
  prep_w2_kernel<<<(NHID * NCLASS + 255) / 256, 256>>>(W2);
  dim3 g1(2, (Nn + 127) / 128);
  gemm1_mma_kernel<<<g1, 256, G1_SMEM>>>(x, b1);
  gemm2_mma_kernel<<<(Nn + 127) / 128, 256>>>(b2);

  zero_counts_kernel<<<(Nn + 255) / 256, 256>>>();
  hist_kernel<<<(Ee + 255) / 256, 256>>>(edst);
  scan1_kernel<<<NB, 256>>>();
  scan2_kernel<<<1, 512>>>();
  scan3_kernel<<<NB, 256>>>();
  scatter_kernel<<<(Ee + 255) / 256, 256>>>(esrc, edst, ev);

  for (int it = 0; it < KHOP; it++)
    spmm_kernel<<<(Nn + 7) / 8, 256>>>(it);

  logsoftmax_kernel<<<(Nn + 7) / 8, 256>>>(out);
}